// round 15
// baseline (speedup 1.0000x reference)
#include <cuda_runtime.h>
#include <cuda_bf16.h>
#include <cstdint>

#define N_SRC 50000
#define M_TGT 50000
#define E_EDGE 400000
#define EMBED 128
#define HEADS 4
#define HH 512            // HEADS*HID
#define HSM_COLS 640      // 512 hidden + 128 message, fused per source node

typedef __nv_bfloat16 bf16;

// ---------------- scratch (device globals; no allocations allowed) ----------
__device__ __align__(256) float g_HSM[(size_t)N_SRC * HSM_COLS];
__device__ __align__(256) float g_HT[(size_t)M_TGT * HH];
__device__ __align__(256) float g_agg[(size_t)M_TGT * EMBED];
__device__ float    g_logits[(size_t)E_EDGE * HEADS];
__device__ unsigned g_mx[(size_t)M_TGT * HEADS];
__device__ float    g_den[(size_t)M_TGT * HEADS];
// CSR sort scratch
__device__ int g_cnt[M_TGT];
__device__ int g_rowstart[M_TGT + 1];
__device__ int g_cursor[M_TGT];
__device__ int g_ssorted[E_EDGE];     // source ids sorted by target
__device__ int g_tsorted[E_EDGE];     // target ids sorted by target

// bf16 hi/lo splits (A operands, k-major [row][128])
__device__ __align__(256) bf16 g_SFh[(size_t)N_SRC * 128];
__device__ __align__(256) bf16 g_SFl[(size_t)N_SRC * 128];
__device__ __align__(256) bf16 g_TFh[(size_t)M_TGT * 128];
__device__ __align__(256) bf16 g_TFl[(size_t)M_TGT * 128];
__device__ __align__(256) bf16 g_AGh[(size_t)M_TGT * 128];
__device__ __align__(256) bf16 g_AGl[(size_t)M_TGT * 128];
// bf16 hi/lo weight splits, n-major (transposed) [col][128]
__device__ __align__(256) bf16 g_Wsmh[(size_t)HSM_COLS * 128];
__device__ __align__(256) bf16 g_Wsml[(size_t)HSM_COLS * 128];
__device__ __align__(256) bf16 g_Wth[(size_t)HH * 128];
__device__ __align__(256) bf16 g_Wtl[(size_t)HH * 128];
__device__ __align__(256) bf16 g_Woh[(size_t)128 * 128];
__device__ __align__(256) bf16 g_Wol[(size_t)128 * 128];
__device__ float g_bsm[HSM_COLS];

// ---------------- helpers ----------------
__device__ __forceinline__ unsigned enc_f32(float f) {
    unsigned u = __float_as_uint(f);
    return (u & 0x80000000u) ? ~u : (u | 0x80000000u);
}
__device__ __forceinline__ float dec_f32(unsigned u) {
    return (u & 0x80000000u) ? __uint_as_float(u & 0x7fffffffu) : __uint_as_float(~u);
}
__device__ __forceinline__ float gelu_exact(float x) {
    return 0.5f * x * (1.0f + erff(x * 0.70710678118654752f));
}
__device__ __forceinline__ void red_add_v4(float* p, float4 v) {
    asm volatile("red.global.add.v4.f32 [%0], {%1, %2, %3, %4};"
                 :: "l"(p), "f"(v.x), "f"(v.y), "f"(v.z), "f"(v.w) : "memory");
}
__device__ __forceinline__ void cp16(uint32_t dst, const void* src, int bytes) {
    asm volatile("cp.async.cg.shared.global [%0], [%1], 16, %2;"
                 :: "r"(dst), "l"(src), "r"(bytes));
}
__device__ __forceinline__ void mma_bf16(float* c, const uint32_t* a,
                                         uint32_t b0, uint32_t b1) {
    asm volatile(
        "mma.sync.aligned.m16n8k16.row.col.f32.bf16.bf16.f32 "
        "{%0,%1,%2,%3}, {%4,%5,%6,%7}, {%8,%9}, {%0,%1,%2,%3};"
        : "+f"(c[0]), "+f"(c[1]), "+f"(c[2]), "+f"(c[3])
        : "r"(a[0]), "r"(a[1]), "r"(a[2]), "r"(a[3]), "r"(b0), "r"(b1));
}

// ---------------- init (also zeroes histogram counters) ----------------
__global__ void init_kernel(float* __restrict__ agg, unsigned* __restrict__ mx,
                            float* __restrict__ den, int* __restrict__ cnt) {
    int i = blockIdx.x * blockDim.x + threadIdx.x;
    if (i < M_TGT * EMBED) agg[i] = 0.0f;
    if (i < M_TGT * HEADS) { mx[i] = 0u; den[i] = 0.0f; }
    if (i < M_TGT) cnt[i] = 0;
}

// ---------------- CSR sort kernels ----------------
__global__ void hist_kernel(const int* __restrict__ etgt, int* __restrict__ cnt) {
    int e = blockIdx.x * blockDim.x + threadIdx.x;
    if (e < E_EDGE) atomicAdd(&cnt[etgt[e]], 1);
}

// Fast single-block scan: thread-sequential chunks + one block scan of totals.
#define SCAN_THREADS 1024
#define SCAN_CHUNK ((M_TGT + SCAN_THREADS - 1) / SCAN_THREADS)   // 49
__global__ __launch_bounds__(SCAN_THREADS) void scan_kernel(
    const int* __restrict__ cnt, int* __restrict__ rowstart,
    int* __restrict__ cursor) {
    __shared__ int wsum[32];
    const int tid = threadIdx.x, lane = tid & 31, wid = tid >> 5;
    const int lo = tid * SCAN_CHUNK;
    const int hi = min(lo + SCAN_CHUNK, M_TGT);

    // pass 1: per-thread chunk total
    int tot = 0;
    for (int i = lo; i < hi; ++i) tot += cnt[i];

    // block-wide exclusive scan of the 1024 totals
    int x = tot;
    #pragma unroll
    for (int off = 1; off < 32; off <<= 1) {
        int y = __shfl_up_sync(0xffffffffu, x, off);
        if (lane >= off) x += y;
    }
    if (lane == 31) wsum[wid] = x;
    __syncthreads();
    if (wid == 0) {
        int w = (lane < 32) ? wsum[lane] : 0;
        #pragma unroll
        for (int off = 1; off < 32; off <<= 1) {
            int y = __shfl_up_sync(0xffffffffu, w, off);
            if (lane >= off) w += y;
        }
        wsum[lane] = w;
    }
    __syncthreads();
    int excl = (wid > 0 ? wsum[wid - 1] : 0) + x - tot;   // exclusive prefix of my chunk

    // pass 2: write exclusive prefixes within the chunk
    int run = excl;
    for (int i = lo; i < hi; ++i) {
        rowstart[i] = run;
        cursor[i] = run;
        run += cnt[i];
    }
    if (tid == SCAN_THREADS - 1) rowstart[M_TGT] = run;
}

__global__ void scatter_edge_kernel(const int* __restrict__ etgt,
                                    const int* __restrict__ esrc,
                                    int* __restrict__ cursor,
                                    int* __restrict__ ssorted,
                                    int* __restrict__ tsorted) {
    int e = blockIdx.x * blockDim.x + threadIdx.x;
    if (e >= E_EDGE) return;
    int t = etgt[e];
    int pos = atomicAdd(&cursor[t], 1);
    ssorted[pos] = esrc[e];
    tsorted[pos] = t;
}

// ---------------- split kernels ----------------
__global__ void split_a_kernel(const float* __restrict__ in, bf16* __restrict__ hi,
                               bf16* __restrict__ lo, int n4) {
    int i = blockIdx.x * blockDim.x + threadIdx.x;
    if (i >= n4) return;
    float4 v = ((const float4*)in)[i];
    bf16 h0 = __float2bfloat16_rn(v.x), h1 = __float2bfloat16_rn(v.y);
    bf16 h2 = __float2bfloat16_rn(v.z), h3 = __float2bfloat16_rn(v.w);
    bf16 l0 = __float2bfloat16_rn(v.x - __bfloat162float(h0));
    bf16 l1 = __float2bfloat16_rn(v.y - __bfloat162float(h1));
    bf16 l2 = __float2bfloat16_rn(v.z - __bfloat162float(h2));
    bf16 l3 = __float2bfloat16_rn(v.w - __bfloat162float(h3));
    __nv_bfloat162* ph = (__nv_bfloat162*)(hi + 4 * (size_t)i);
    __nv_bfloat162* pl = (__nv_bfloat162*)(lo + 4 * (size_t)i);
    __nv_bfloat162 a; a.x = h0; a.y = h1; ph[0] = a;
    __nv_bfloat162 b; b.x = h2; b.y = h3; ph[1] = b;
    __nv_bfloat162 c; c.x = l0; c.y = l1; pl[0] = c;
    __nv_bfloat162 d; d.x = l2; d.y = l3; pl[1] = d;
}
__global__ void split_w_t_kernel(const float* __restrict__ W, bf16* __restrict__ Ht,
                                 bf16* __restrict__ Lt, int cols, int row0) {
    int i = blockIdx.x * blockDim.x + threadIdx.x;
    if (i >= cols * 128) return;
    int n = i >> 7, k = i & 127;
    float v = W[(size_t)k * cols + n];
    bf16 h = __float2bfloat16_rn(v);
    bf16 l = __float2bfloat16_rn(v - __bfloat162float(h));
    Ht[(size_t)(row0 + n) * 128 + k] = h;
    Lt[(size_t)(row0 + n) * 128 + k] = l;
}
__global__ void concat_bias_kernel(const float* __restrict__ bs,
                                   const float* __restrict__ bm,
                                   float* __restrict__ dst) {
    int i = blockIdx.x * blockDim.x + threadIdx.x;
    if (i < HH) dst[i] = bs[i];
    else if (i < HSM_COLS) dst[i] = bm[i - HH];
}

// ---------------- bf16x3 tensor-core GEMM, cp.async double-buffered ----------
#define ST 20
#define STAGE_W 10240
#define A_HOFF 0
#define A_LOFF 2560
#define B_HOFF 5120
#define B_LOFF 7680
#define GEMM_SMEM_BYTES (2 * STAGE_W * 4)

__global__ __launch_bounds__(256, 2) void gemm_bf16x3(
    const bf16* __restrict__ Ah, const bf16* __restrict__ Al,
    const bf16* __restrict__ Bh, const bf16* __restrict__ Bl,
    const float* __restrict__ bias, float* __restrict__ C,
    int rows, int cols) {
    extern __shared__ uint32_t smw[];
    const uint32_t smem_u32 = (uint32_t)__cvta_generic_to_shared(smw);
    const int tid = threadIdx.x, lane = tid & 31, warp = tid >> 5;
    const int wm = warp >> 1, wn = warp & 1;
    const int g = lane >> 2, q = lane & 3;
    const int row0 = blockIdx.x * 128, col0 = blockIdx.y * 128;

    float acc[2][8][4] = {};

    auto fill = [&](int stage, int kt) {
        uint32_t base = smem_u32 + stage * STAGE_W * 4;
        #pragma unroll
        for (int it = 0; it < 4; ++it) {
            int idx = tid + it * 256;
            int half = idx >> 9;
            int j = idx & 511;
            int m = j >> 2, c = j & 3;
            const bf16* src = (half ? Al : Ah) + (size_t)(row0 + m) * 128 + kt * 32 + c * 8;
            uint32_t dst = base + (half ? A_LOFF : A_HOFF) * 4 + (m * ST + c * 4) * 4;
            cp16(dst, src, (row0 + m) < rows ? 16 : 0);
        }
        #pragma unroll
        for (int it = 0; it < 4; ++it) {
            int idx = tid + it * 256;
            int half = idx >> 9;
            int j = idx & 511;
            int n = j >> 2, c = j & 3;
            const bf16* src = (half ? Bl : Bh) + (size_t)(col0 + n) * 128 + kt * 32 + c * 8;
            uint32_t dst = base + (half ? B_LOFF : B_HOFF) * 4 + (n * ST + c * 4) * 4;
            cp16(dst, src, 16);
        }
    };

    fill(0, 0);
    asm volatile("cp.async.commit_group;");

    #pragma unroll
    for (int kt = 0; kt < 4; ++kt) {
        if (kt < 3) {
            fill((kt + 1) & 1, kt + 1);
            asm volatile("cp.async.commit_group;");
            asm volatile("cp.async.wait_group 1;");
        } else {
            asm volatile("cp.async.wait_group 0;");
        }
        __syncthreads();
        const uint32_t* sb = smw + (kt & 1) * STAGE_W;
        #pragma unroll
        for (int ks = 0; ks < 2; ++ks) {
            const int k0 = ks * 8;
            uint32_t ah[2][4], al[2][4];
            #pragma unroll
            for (int mt = 0; mt < 2; ++mt) {
                const uint32_t* ph = sb + A_HOFF + (wm * 32 + mt * 16 + g) * ST + k0 + q;
                ah[mt][0] = ph[0]; ah[mt][1] = ph[8 * ST];
                ah[mt][2] = ph[4]; ah[mt][3] = ph[8 * ST + 4];
                const uint32_t* pl = sb + A_LOFF + (wm * 32 + mt * 16 + g) * ST + k0 + q;
                al[mt][0] = pl[0]; al[mt][1] = pl[8 * ST];
                al[mt][2] = pl[4]; al[mt][3] = pl[8 * ST + 4];
            }
            #pragma unroll
            for (int nt = 0; nt < 8; ++nt) {
                const uint32_t* pb = sb + B_HOFF + (wn * 64 + nt * 8 + g) * ST + k0 + q;
                uint32_t bh0 = pb[0], bh1 = pb[4];
                const uint32_t* pbl = sb + B_LOFF + (wn * 64 + nt * 8 + g) * ST + k0 + q;
                uint32_t bl0 = pbl[0], bl1 = pbl[4];
                #pragma unroll
                for (int mt = 0; mt < 2; ++mt) {
                    mma_bf16(acc[mt][nt], ah[mt], bl0, bl1);
                    mma_bf16(acc[mt][nt], al[mt], bh0, bh1);
                    mma_bf16(acc[mt][nt], ah[mt], bh0, bh1);
                }
            }
        }
        __syncthreads();
    }

    #pragma unroll
    for (int nt = 0; nt < 8; ++nt) {
        int c = col0 + wn * 64 + nt * 8 + q * 2;
        float b0 = __ldg(bias + c), b1 = __ldg(bias + c + 1);
        #pragma unroll
        for (int mt = 0; mt < 2; ++mt) {
            int r = row0 + wm * 32 + mt * 16 + g;
            if (r < rows)
                *(float2*)(C + (size_t)r * cols + c) =
                    make_float2(acc[mt][nt][0] + b0, acc[mt][nt][1] + b1);
            if (r + 8 < rows)
                *(float2*)(C + (size_t)(r + 8) * cols + c) =
                    make_float2(acc[mt][nt][2] + b0, acc[mt][nt][3] + b1);
        }
    }
}

// ---------------- edge pass 1: logits + segment max (sorted edges) ----------
__global__ __launch_bounds__(256) void edge_logits_kernel(
    const float* __restrict__ HSM, const float* __restrict__ HT,
    const int* __restrict__ tsorted, const int* __restrict__ ssorted,
    const float* __restrict__ attn_w,
    float* __restrict__ logits, unsigned* __restrict__ mx) {
    __shared__ float aw[HH];
    const int tid = threadIdx.x;
    for (int i = tid; i < HH; i += 256) aw[i] = attn_w[i];
    __syncthreads();

    const int warp = tid >> 5, lane = tid & 31;
    const int e = blockIdx.x * 8 + warp;
    if (e >= E_EDGE) return;
    const int s = ssorted[e];
    const int t = tsorted[e];

    const float4* ps = (const float4*)(HSM + (size_t)s * HSM_COLS) + lane * 4;
    const float4* pt = (const float4*)(HT + (size_t)t * HH) + lane * 4;
    const float4* pw = (const float4*)(aw) + lane * 4;

    float partial = 0.0f;
    #pragma unroll
    for (int q = 0; q < 4; ++q) {
        float4 a = ps[q];
        float4 b = pt[q];
        float4 w = pw[q];
        partial += gelu_exact(a.x + b.x) * w.x;
        partial += gelu_exact(a.y + b.y) * w.y;
        partial += gelu_exact(a.z + b.z) * w.z;
        partial += gelu_exact(a.w + b.w) * w.w;
    }
    #pragma unroll
    for (int off = 4; off > 0; off >>= 1)
        partial += __shfl_down_sync(0xffffffffu, partial, off, 8);
    if ((lane & 7) == 0) {
        int head = lane >> 3;
        logits[(size_t)e * HEADS + head] = partial;
        atomicMax(&mx[(size_t)t * HEADS + head], enc_f32(partial));
    }
}

// ---------------- edge pass 2: exp + segment sum ----------------
__global__ void softmax_den_kernel(
    float* __restrict__ logits, const int* __restrict__ tsorted,
    const unsigned* __restrict__ mx, float* __restrict__ den) {
    int i = blockIdx.x * blockDim.x + threadIdx.x;
    if (i >= E_EDGE * HEADS) return;
    int e = i >> 2, h = i & 3;
    int t = tsorted[e];
    float m = dec_f32(mx[(size_t)t * HEADS + h]);
    float v = expf(logits[i] - m);
    logits[i] = v;
    atomicAdd(&den[(size_t)t * HEADS + h], v);
}

// ---------------- edge pass 3: weighted message scatter ----------------
__global__ __launch_bounds__(256) void scatter_msgs_kernel(
    const float* __restrict__ HSM, const float* __restrict__ ex,
    const float* __restrict__ den, const int* __restrict__ tsorted,
    const int* __restrict__ ssorted, float* __restrict__ agg) {
    const int tid = threadIdx.x;
    const int warp = tid >> 5, lane = tid & 31;
    const int e = blockIdx.x * 8 + warp;
    if (e >= E_EDGE) return;
    const int s = ssorted[e];
    const int t = tsorted[e];
    const int head = lane >> 3;
    float score = ex[(size_t)e * HEADS + head] / den[(size_t)t * HEADS + head];
    float4 m = *(const float4*)(HSM + (size_t)s * HSM_COLS + HH + lane * 4);
    float4 v;
    v.x = m.x * score; v.y = m.y * score; v.z = m.z * score; v.w = m.w * score;
    red_add_v4(agg + (size_t)t * EMBED + lane * 4, v);
}

// ---------------- launch ----------------
extern "C" void kernel_launch(void* const* d_in, const int* in_sizes, int n_in,
                              void* d_out, int out_size) {
    const float* SF   = (const float*)d_in[0];
    const float* TF   = (const float*)d_in[1];
    const int*   etgt = (const int*)d_in[2];
    const int*   esrc = (const int*)d_in[3];
    const float* Ws   = (const float*)d_in[4];
    const float* bs   = (const float*)d_in[5];
    const float* Wt   = (const float*)d_in[6];
    const float* bt   = (const float*)d_in[7];
    const float* attn = (const float*)d_in[8];
    const float* Wm   = (const float*)d_in[9];
    const float* bm   = (const float*)d_in[10];
    const float* Wo   = (const float*)d_in[11];
    const float* bo   = (const float*)d_in[12];
    float* out = (float*)d_out;

    float *hsm, *ht, *agg, *bsm, *logits, *den;
    unsigned* mx;
    int *cnt, *rowstart, *cursor, *ssorted, *tsorted;
    bf16 *sfh, *sfl, *tfh, *tfl, *agh, *agl;
    bf16 *wsmh, *wsml, *wth, *wtl, *woh, *wol;
    cudaGetSymbolAddress((void**)&hsm, g_HSM);
    cudaGetSymbolAddress((void**)&ht, g_HT);
    cudaGetSymbolAddress((void**)&agg, g_agg);
    cudaGetSymbolAddress((void**)&bsm, g_bsm);
    cudaGetSymbolAddress((void**)&logits, g_logits);
    cudaGetSymbolAddress((void**)&mx, g_mx);
    cudaGetSymbolAddress((void**)&den, g_den);
    cudaGetSymbolAddress((void**)&cnt, g_cnt);
    cudaGetSymbolAddress((void**)&rowstart, g_rowstart);
    cudaGetSymbolAddress((void**)&cursor, g_cursor);
    cudaGetSymbolAddress((void**)&ssorted, g_ssorted);
    cudaGetSymbolAddress((void**)&tsorted, g_tsorted);
    cudaGetSymbolAddress((void**)&sfh, g_SFh);  cudaGetSymbolAddress((void**)&sfl, g_SFl);
    cudaGetSymbolAddress((void**)&tfh, g_TFh);  cudaGetSymbolAddress((void**)&tfl, g_TFl);
    cudaGetSymbolAddress((void**)&agh, g_AGh);  cudaGetSymbolAddress((void**)&agl, g_AGl);
    cudaGetSymbolAddress((void**)&wsmh, g_Wsmh); cudaGetSymbolAddress((void**)&wsml, g_Wsml);
    cudaGetSymbolAddress((void**)&wth, g_Wth);  cudaGetSymbolAddress((void**)&wtl, g_Wtl);
    cudaGetSymbolAddress((void**)&woh, g_Woh);  cudaGetSymbolAddress((void**)&wol, g_Wol);

    cudaFuncSetAttribute(gemm_bf16x3,
                         cudaFuncAttributeMaxDynamicSharedMemorySize,
                         GEMM_SMEM_BYTES);

    const int mtiles = (N_SRC + 127) / 128;   // 391
    const int n4 = N_SRC * 32;

    // init (agg/mx/den/cnt) + CSR sort
    init_kernel<<<(M_TGT * EMBED + 255) / 256, 256>>>(agg, mx, den, cnt);
    hist_kernel<<<(E_EDGE + 255) / 256, 256>>>(etgt, cnt);
    scan_kernel<<<1, SCAN_THREADS>>>(cnt, rowstart, cursor);
    scatter_edge_kernel<<<(E_EDGE + 255) / 256, 256>>>(etgt, esrc, cursor, ssorted, tsorted);

    // operand prep
    split_a_kernel<<<(n4 + 255) / 256, 256>>>(SF, sfh, sfl, n4);
    split_a_kernel<<<(n4 + 255) / 256, 256>>>(TF, tfh, tfl, n4);
    split_w_t_kernel<<<(HH * 128 + 255) / 256, 256>>>(Ws, wsmh, wsml, HH, 0);
    split_w_t_kernel<<<(128 * 128 + 255) / 256, 256>>>(Wm, wsmh, wsml, 128, HH);
    split_w_t_kernel<<<(HH * 128 + 255) / 256, 256>>>(Wt, wth, wtl, HH, 0);
    split_w_t_kernel<<<(128 * 128 + 255) / 256, 256>>>(Wo, woh, wol, 128, 0);
    concat_bias_kernel<<<3, 256>>>(bs, bm, bsm);

    // node-level GEMMs
    gemm_bf16x3<<<dim3(mtiles, HSM_COLS / 128), 256, GEMM_SMEM_BYTES>>>(
        sfh, sfl, wsmh, wsml, bsm, hsm, N_SRC, HSM_COLS);
    gemm_bf16x3<<<dim3(mtiles, HH / 128), 256, GEMM_SMEM_BYTES>>>(
        tfh, tfl, wth, wtl, bt, ht, M_TGT, HH);

    // edge phase over sorted edges
    edge_logits_kernel<<<E_EDGE / 8, 256>>>(hsm, ht, tsorted, ssorted, attn, logits, mx);
    softmax_den_kernel<<<(E_EDGE * HEADS + 255) / 256, 256>>>(logits, tsorted, mx, den);
    scatter_msgs_kernel<<<E_EDGE / 8, 256>>>(hsm, logits, den, tsorted, ssorted, agg);

    // output GEMM
    split_a_kernel<<<(n4 + 255) / 256, 256>>>(agg, agh, agl, n4);
    gemm_bf16x3<<<dim3(mtiles, 1), 256, GEMM_SMEM_BYTES>>>(
        agh, agl, woh, wol, bo, out, M_TGT, EMBED);
}

// round 16
// speedup vs baseline: 1.1343x; 1.1343x over previous
#include <cuda_runtime.h>
#include <cuda_bf16.h>
#include <cstdint>

#define N_SRC 50000
#define M_TGT 50000
#define E_EDGE 400000
#define EMBED 128
#define HEADS 4
#define HH 512            // HEADS*HID
#define HSM_COLS 640      // 512 hidden + 128 message, fused per source node

typedef __nv_bfloat16 bf16;

// ---------------- scratch (device globals; no allocations allowed) ----------
__device__ __align__(256) float g_HSM[(size_t)N_SRC * HSM_COLS];
__device__ __align__(256) float g_HT[(size_t)M_TGT * HH];
__device__ __align__(256) float g_agg[(size_t)M_TGT * EMBED];
__device__ float    g_logits[(size_t)E_EDGE * HEADS];
__device__ unsigned g_mx[(size_t)M_TGT * HEADS];
__device__ float    g_den[(size_t)M_TGT * HEADS];

// bf16 hi/lo splits (A operands, k-major [row][128])
__device__ __align__(256) bf16 g_SFh[(size_t)N_SRC * 128];
__device__ __align__(256) bf16 g_SFl[(size_t)N_SRC * 128];
__device__ __align__(256) bf16 g_TFh[(size_t)M_TGT * 128];
__device__ __align__(256) bf16 g_TFl[(size_t)M_TGT * 128];
__device__ __align__(256) bf16 g_AGh[(size_t)M_TGT * 128];
__device__ __align__(256) bf16 g_AGl[(size_t)M_TGT * 128];
// bf16 hi/lo weight splits, n-major (transposed) [col][128]
__device__ __align__(256) bf16 g_Wsmh[(size_t)HSM_COLS * 128];
__device__ __align__(256) bf16 g_Wsml[(size_t)HSM_COLS * 128];
__device__ __align__(256) bf16 g_Wth[(size_t)HH * 128];
__device__ __align__(256) bf16 g_Wtl[(size_t)HH * 128];
__device__ __align__(256) bf16 g_Woh[(size_t)128 * 128];
__device__ __align__(256) bf16 g_Wol[(size_t)128 * 128];
__device__ float g_bsm[HSM_COLS];

// ---------------- helpers ----------------
__device__ __forceinline__ unsigned enc_f32(float f) {
    unsigned u = __float_as_uint(f);
    return (u & 0x80000000u) ? ~u : (u | 0x80000000u);
}
__device__ __forceinline__ float dec_f32(unsigned u) {
    return (u & 0x80000000u) ? __uint_as_float(u & 0x7fffffffu) : __uint_as_float(~u);
}
// Branch-free erf (Abramowitz-Stegun 7.1.26, |err| <= 1.5e-7), then exact GELU.
__device__ __forceinline__ float erf_fast(float x) {
    float ax = fabsf(x);
    float t  = __fdividef(1.0f, fmaf(0.3275911f, ax, 1.0f));
    float p  = fmaf(t, 1.061405429f, -1.453152027f);
    p = fmaf(t, p, 1.421413741f);
    p = fmaf(t, p, -0.284496736f);
    p = fmaf(t, p, 0.254829592f);
    p = p * t;
    float r = fmaf(-p, __expf(-ax * ax), 1.0f);
    return copysignf(r, x);
}
__device__ __forceinline__ float gelu_exact(float x) {
    return 0.5f * x * (1.0f + erf_fast(x * 0.70710678118654752f));
}
__device__ __forceinline__ void red_add_v4(float* p, float4 v) {
    asm volatile("red.global.add.v4.f32 [%0], {%1, %2, %3, %4};"
                 :: "l"(p), "f"(v.x), "f"(v.y), "f"(v.z), "f"(v.w) : "memory");
}
__device__ __forceinline__ void cp16(uint32_t dst, const void* src, int bytes) {
    asm volatile("cp.async.cg.shared.global [%0], [%1], 16, %2;"
                 :: "r"(dst), "l"(src), "r"(bytes));
}
__device__ __forceinline__ void mma_bf16(float* c, const uint32_t* a,
                                         uint32_t b0, uint32_t b1) {
    asm volatile(
        "mma.sync.aligned.m16n8k16.row.col.f32.bf16.bf16.f32 "
        "{%0,%1,%2,%3}, {%4,%5,%6,%7}, {%8,%9}, {%0,%1,%2,%3};"
        : "+f"(c[0]), "+f"(c[1]), "+f"(c[2]), "+f"(c[3])
        : "r"(a[0]), "r"(a[1]), "r"(a[2]), "r"(a[3]), "r"(b0), "r"(b1));
}

// ---------------- init ----------------
__global__ void init_kernel(float* __restrict__ agg, unsigned* __restrict__ mx,
                            float* __restrict__ den) {
    int i = blockIdx.x * blockDim.x + threadIdx.x;
    if (i < M_TGT * EMBED) agg[i] = 0.0f;
    if (i < M_TGT * HEADS) { mx[i] = 0u; den[i] = 0.0f; }
}

// ---------------- split kernels ----------------
__global__ void split_a_kernel(const float* __restrict__ in, bf16* __restrict__ hi,
                               bf16* __restrict__ lo, int n4) {
    int i = blockIdx.x * blockDim.x + threadIdx.x;
    if (i >= n4) return;
    float4 v = ((const float4*)in)[i];
    bf16 h0 = __float2bfloat16_rn(v.x), h1 = __float2bfloat16_rn(v.y);
    bf16 h2 = __float2bfloat16_rn(v.z), h3 = __float2bfloat16_rn(v.w);
    bf16 l0 = __float2bfloat16_rn(v.x - __bfloat162float(h0));
    bf16 l1 = __float2bfloat16_rn(v.y - __bfloat162float(h1));
    bf16 l2 = __float2bfloat16_rn(v.z - __bfloat162float(h2));
    bf16 l3 = __float2bfloat16_rn(v.w - __bfloat162float(h3));
    __nv_bfloat162* ph = (__nv_bfloat162*)(hi + 4 * (size_t)i);
    __nv_bfloat162* pl = (__nv_bfloat162*)(lo + 4 * (size_t)i);
    __nv_bfloat162 a; a.x = h0; a.y = h1; ph[0] = a;
    __nv_bfloat162 b; b.x = h2; b.y = h3; ph[1] = b;
    __nv_bfloat162 c; c.x = l0; c.y = l1; pl[0] = c;
    __nv_bfloat162 d; d.x = l2; d.y = l3; pl[1] = d;
}
__global__ void split_w_t_kernel(const float* __restrict__ W, bf16* __restrict__ Ht,
                                 bf16* __restrict__ Lt, int cols, int row0) {
    int i = blockIdx.x * blockDim.x + threadIdx.x;
    if (i >= cols * 128) return;
    int n = i >> 7, k = i & 127;
    float v = W[(size_t)k * cols + n];
    bf16 h = __float2bfloat16_rn(v);
    bf16 l = __float2bfloat16_rn(v - __bfloat162float(h));
    Ht[(size_t)(row0 + n) * 128 + k] = h;
    Lt[(size_t)(row0 + n) * 128 + k] = l;
}
__global__ void concat_bias_kernel(const float* __restrict__ bs,
                                   const float* __restrict__ bm,
                                   float* __restrict__ dst) {
    int i = blockIdx.x * blockDim.x + threadIdx.x;
    if (i < HH) dst[i] = bs[i];
    else if (i < HSM_COLS) dst[i] = bm[i - HH];
}

// ---------------- bf16x3 tensor-core GEMM, cp.async double-buffered ----------
#define ST 20
#define STAGE_W 10240
#define A_HOFF 0
#define A_LOFF 2560
#define B_HOFF 5120
#define B_LOFF 7680
#define GEMM_SMEM_BYTES (2 * STAGE_W * 4)

__global__ __launch_bounds__(256, 2) void gemm_bf16x3(
    const bf16* __restrict__ Ah, const bf16* __restrict__ Al,
    const bf16* __restrict__ Bh, const bf16* __restrict__ Bl,
    const float* __restrict__ bias, float* __restrict__ C,
    int rows, int cols) {
    extern __shared__ uint32_t smw[];
    const uint32_t smem_u32 = (uint32_t)__cvta_generic_to_shared(smw);
    const int tid = threadIdx.x, lane = tid & 31, warp = tid >> 5;
    const int wm = warp >> 1, wn = warp & 1;
    const int g = lane >> 2, q = lane & 3;
    const int row0 = blockIdx.x * 128, col0 = blockIdx.y * 128;

    float acc[2][8][4] = {};

    auto fill = [&](int stage, int kt) {
        uint32_t base = smem_u32 + stage * STAGE_W * 4;
        #pragma unroll
        for (int it = 0; it < 4; ++it) {
            int idx = tid + it * 256;
            int half = idx >> 9;
            int j = idx & 511;
            int m = j >> 2, c = j & 3;
            const bf16* src = (half ? Al : Ah) + (size_t)(row0 + m) * 128 + kt * 32 + c * 8;
            uint32_t dst = base + (half ? A_LOFF : A_HOFF) * 4 + (m * ST + c * 4) * 4;
            cp16(dst, src, (row0 + m) < rows ? 16 : 0);
        }
        #pragma unroll
        for (int it = 0; it < 4; ++it) {
            int idx = tid + it * 256;
            int half = idx >> 9;
            int j = idx & 511;
            int n = j >> 2, c = j & 3;
            const bf16* src = (half ? Bl : Bh) + (size_t)(col0 + n) * 128 + kt * 32 + c * 8;
            uint32_t dst = base + (half ? B_LOFF : B_HOFF) * 4 + (n * ST + c * 4) * 4;
            cp16(dst, src, 16);
        }
    };

    fill(0, 0);
    asm volatile("cp.async.commit_group;");

    #pragma unroll
    for (int kt = 0; kt < 4; ++kt) {
        if (kt < 3) {
            fill((kt + 1) & 1, kt + 1);
            asm volatile("cp.async.commit_group;");
            asm volatile("cp.async.wait_group 1;");
        } else {
            asm volatile("cp.async.wait_group 0;");
        }
        __syncthreads();
        const uint32_t* sb = smw + (kt & 1) * STAGE_W;
        #pragma unroll
        for (int ks = 0; ks < 2; ++ks) {
            const int k0 = ks * 8;
            uint32_t ah[2][4], al[2][4];
            #pragma unroll
            for (int mt = 0; mt < 2; ++mt) {
                const uint32_t* ph = sb + A_HOFF + (wm * 32 + mt * 16 + g) * ST + k0 + q;
                ah[mt][0] = ph[0]; ah[mt][1] = ph[8 * ST];
                ah[mt][2] = ph[4]; ah[mt][3] = ph[8 * ST + 4];
                const uint32_t* pl = sb + A_LOFF + (wm * 32 + mt * 16 + g) * ST + k0 + q;
                al[mt][0] = pl[0]; al[mt][1] = pl[8 * ST];
                al[mt][2] = pl[4]; al[mt][3] = pl[8 * ST + 4];
            }
            #pragma unroll
            for (int nt = 0; nt < 8; ++nt) {
                const uint32_t* pb = sb + B_HOFF + (wn * 64 + nt * 8 + g) * ST + k0 + q;
                uint32_t bh0 = pb[0], bh1 = pb[4];
                const uint32_t* pbl = sb + B_LOFF + (wn * 64 + nt * 8 + g) * ST + k0 + q;
                uint32_t bl0 = pbl[0], bl1 = pbl[4];
                #pragma unroll
                for (int mt = 0; mt < 2; ++mt) {
                    mma_bf16(acc[mt][nt], ah[mt], bl0, bl1);
                    mma_bf16(acc[mt][nt], al[mt], bh0, bh1);
                    mma_bf16(acc[mt][nt], ah[mt], bh0, bh1);
                }
            }
        }
        __syncthreads();
    }

    #pragma unroll
    for (int nt = 0; nt < 8; ++nt) {
        int c = col0 + wn * 64 + nt * 8 + q * 2;
        float b0 = __ldg(bias + c), b1 = __ldg(bias + c + 1);
        #pragma unroll
        for (int mt = 0; mt < 2; ++mt) {
            int r = row0 + wm * 32 + mt * 16 + g;
            if (r < rows)
                *(float2*)(C + (size_t)r * cols + c) =
                    make_float2(acc[mt][nt][0] + b0, acc[mt][nt][1] + b1);
            if (r + 8 < rows)
                *(float2*)(C + (size_t)(r + 8) * cols + c) =
                    make_float2(acc[mt][nt][2] + b0, acc[mt][nt][3] + b1);
        }
    }
}

// ---------------- edge pass 1: logits + segment max ----------------
__global__ __launch_bounds__(256) void edge_logits_kernel(
    const float* __restrict__ HSM, const float* __restrict__ HT,
    const int* __restrict__ etgt, const int* __restrict__ esrc,
    const float* __restrict__ attn_w,
    float* __restrict__ logits, unsigned* __restrict__ mx) {
    __shared__ float aw[HH];
    const int tid = threadIdx.x;
    for (int i = tid; i < HH; i += 256) aw[i] = attn_w[i];
    __syncthreads();

    const int warp = tid >> 5, lane = tid & 31;
    const int e = blockIdx.x * 8 + warp;
    if (e >= E_EDGE) return;
    const int s = esrc[e];
    const int t = etgt[e];

    const float4* ps = (const float4*)(HSM + (size_t)s * HSM_COLS) + lane * 4;
    const float4* pt = (const float4*)(HT + (size_t)t * HH) + lane * 4;
    const float4* pw = (const float4*)(aw) + lane * 4;

    float partial = 0.0f;
    #pragma unroll
    for (int q = 0; q < 4; ++q) {
        float4 a = ps[q];
        float4 b = pt[q];
        float4 w = pw[q];
        partial += gelu_exact(a.x + b.x) * w.x;
        partial += gelu_exact(a.y + b.y) * w.y;
        partial += gelu_exact(a.z + b.z) * w.z;
        partial += gelu_exact(a.w + b.w) * w.w;
    }
    #pragma unroll
    for (int off = 4; off > 0; off >>= 1)
        partial += __shfl_down_sync(0xffffffffu, partial, off, 8);
    if ((lane & 7) == 0) {
        int head = lane >> 3;
        logits[(size_t)e * HEADS + head] = partial;
        atomicMax(&mx[(size_t)t * HEADS + head], enc_f32(partial));
    }
}

// ---------------- edge pass 2: exp + segment sum ----------------
__global__ void softmax_den_kernel(
    float* __restrict__ logits, const int* __restrict__ etgt,
    const unsigned* __restrict__ mx, float* __restrict__ den) {
    int i = blockIdx.x * blockDim.x + threadIdx.x;
    if (i >= E_EDGE * HEADS) return;
    int e = i >> 2, h = i & 3;
    int t = etgt[e];
    float m = dec_f32(mx[(size_t)t * HEADS + h]);
    float v = __expf(logits[i] - m);
    logits[i] = v;
    atomicAdd(&den[(size_t)t * HEADS + h], v);
}

// ---------------- edge pass 3: weighted message scatter ----------------
__global__ __launch_bounds__(256) void scatter_msgs_kernel(
    const float* __restrict__ HSM, const float* __restrict__ ex,
    const float* __restrict__ den, const int* __restrict__ etgt,
    const int* __restrict__ esrc, float* __restrict__ agg) {
    const int tid = threadIdx.x;
    const int warp = tid >> 5, lane = tid & 31;
    const int e = blockIdx.x * 8 + warp;
    if (e >= E_EDGE) return;
    const int s = esrc[e];
    const int t = etgt[e];
    const int head = lane >> 3;
    float score = ex[(size_t)e * HEADS + head] / den[(size_t)t * HEADS + head];
    float4 m = *(const float4*)(HSM + (size_t)s * HSM_COLS + HH + lane * 4);
    float4 v;
    v.x = m.x * score; v.y = m.y * score; v.z = m.z * score; v.w = m.w * score;
    red_add_v4(agg + (size_t)t * EMBED + lane * 4, v);
}

// ---------------- launch ----------------
extern "C" void kernel_launch(void* const* d_in, const int* in_sizes, int n_in,
                              void* d_out, int out_size) {
    const float* SF   = (const float*)d_in[0];
    const float* TF   = (const float*)d_in[1];
    const int*   etgt = (const int*)d_in[2];
    const int*   esrc = (const int*)d_in[3];
    const float* Ws   = (const float*)d_in[4];
    const float* bs   = (const float*)d_in[5];
    const float* Wt   = (const float*)d_in[6];
    const float* bt   = (const float*)d_in[7];
    const float* attn = (const float*)d_in[8];
    const float* Wm   = (const float*)d_in[9];
    const float* bm   = (const float*)d_in[10];
    const float* Wo   = (const float*)d_in[11];
    const float* bo   = (const float*)d_in[12];
    float* out = (float*)d_out;

    float *hsm, *ht, *agg, *bsm, *logits, *den;
    unsigned* mx;
    bf16 *sfh, *sfl, *tfh, *tfl, *agh, *agl;
    bf16 *wsmh, *wsml, *wth, *wtl, *woh, *wol;
    cudaGetSymbolAddress((void**)&hsm, g_HSM);
    cudaGetSymbolAddress((void**)&ht, g_HT);
    cudaGetSymbolAddress((void**)&agg, g_agg);
    cudaGetSymbolAddress((void**)&bsm, g_bsm);
    cudaGetSymbolAddress((void**)&logits, g_logits);
    cudaGetSymbolAddress((void**)&mx, g_mx);
    cudaGetSymbolAddress((void**)&den, g_den);
    cudaGetSymbolAddress((void**)&sfh, g_SFh);  cudaGetSymbolAddress((void**)&sfl, g_SFl);
    cudaGetSymbolAddress((void**)&tfh, g_TFh);  cudaGetSymbolAddress((void**)&tfl, g_TFl);
    cudaGetSymbolAddress((void**)&agh, g_AGh);  cudaGetSymbolAddress((void**)&agl, g_AGl);
    cudaGetSymbolAddress((void**)&wsmh, g_Wsmh); cudaGetSymbolAddress((void**)&wsml, g_Wsml);
    cudaGetSymbolAddress((void**)&wth, g_Wth);  cudaGetSymbolAddress((void**)&wtl, g_Wtl);
    cudaGetSymbolAddress((void**)&woh, g_Woh);  cudaGetSymbolAddress((void**)&wol, g_Wol);

    cudaFuncSetAttribute(gemm_bf16x3,
                         cudaFuncAttributeMaxDynamicSharedMemorySize,
                         GEMM_SMEM_BYTES);

    const int mtiles = (N_SRC + 127) / 128;   // 391
    const int n4 = N_SRC * 32;

    init_kernel<<<(M_TGT * EMBED + 255) / 256, 256>>>(agg, mx, den);

    // operand prep
    split_a_kernel<<<(n4 + 255) / 256, 256>>>(SF, sfh, sfl, n4);
    split_a_kernel<<<(n4 + 255) / 256, 256>>>(TF, tfh, tfl, n4);
    split_w_t_kernel<<<(HH * 128 + 255) / 256, 256>>>(Ws, wsmh, wsml, HH, 0);
    split_w_t_kernel<<<(128 * 128 + 255) / 256, 256>>>(Wm, wsmh, wsml, 128, HH);
    split_w_t_kernel<<<(HH * 128 + 255) / 256, 256>>>(Wt, wth, wtl, HH, 0);
    split_w_t_kernel<<<(128 * 128 + 255) / 256, 256>>>(Wo, woh, wol, 128, 0);
    concat_bias_kernel<<<3, 256>>>(bs, bm, bsm);

    // node-level GEMMs
    gemm_bf16x3<<<dim3(mtiles, HSM_COLS / 128), 256, GEMM_SMEM_BYTES>>>(
        sfh, sfl, wsmh, wsml, bsm, hsm, N_SRC, HSM_COLS);
    gemm_bf16x3<<<dim3(mtiles, HH / 128), 256, GEMM_SMEM_BYTES>>>(
        tfh, tfl, wth, wtl, bt, ht, M_TGT, HH);

    // edge phase
    edge_logits_kernel<<<E_EDGE / 8, 256>>>(hsm, ht, etgt, esrc, attn, logits, mx);
    softmax_den_kernel<<<(E_EDGE * HEADS + 255) / 256, 256>>>(logits, etgt, mx, den);
    scatter_msgs_kernel<<<E_EDGE / 8, 256>>>(hsm, logits, den, etgt, esrc, agg);

    // output GEMM
    split_a_kernel<<<(n4 + 255) / 256, 256>>>(agg, agh, agl, n4);
    gemm_bf16x3<<<dim3(mtiles, 1), 256, GEMM_SMEM_BYTES>>>(
        agh, agl, woh, wol, bo, out, M_TGT, EMBED);
}